// round 8
// baseline (speedup 1.0000x reference)
#include <cuda_runtime.h>
#include <cuda_fp16.h>
#include <math.h>
#include <stdint.h>

// Problem constants
#define BATCH 32
#define SEQ   128
#define WL    20
#define D     300
#define DPAD  320
#define M_SEQ (BATCH*SEQ*WL)      // 81920
#define M_VEC (BATCH*SEQ)         // 4096
#define NEG_INF -1000000000.0f

// Scratch (__device__ globals — no cudaMalloc allowed)
__device__ float g_vecpart[M_VEC * D];
__device__ float g_score[M_SEQ];
__device__ __align__(16) __half g_Ws[DPAD * DPAD];
__device__ __align__(16) __half g_Wv[DPAD * DPAD];
__device__ __align__(16) __half g_seqh[(size_t)M_SEQ * DPAD];
__device__ __align__(16) __half g_vech[(size_t)M_VEC * DPAD];

// ---------------------------------------------------------------------------
// PTX helpers (sm_80-era — valid at plain sm_103 target)
// ---------------------------------------------------------------------------
__device__ __forceinline__ uint32_t smem_u32(const void* p) {
    uint32_t a;
    asm("{ .reg .u64 t; cvta.to.shared.u64 t, %1; cvt.u32.u64 %0, t; }" : "=r"(a) : "l"(p));
    return a;
}
__device__ __forceinline__ void ldsm_x4(uint32_t* r, uint32_t addr) {
    asm volatile("ldmatrix.sync.aligned.m8n8.x4.shared.b16 {%0,%1,%2,%3}, [%4];"
                 : "=r"(r[0]), "=r"(r[1]), "=r"(r[2]), "=r"(r[3]) : "r"(addr));
}
__device__ __forceinline__ void mma_f16(float* c, const uint32_t* a, const uint32_t* b) {
    asm volatile("mma.sync.aligned.m16n8k16.row.col.f32.f16.f16.f32 "
                 "{%0,%1,%2,%3}, {%4,%5,%6,%7}, {%8,%9}, {%0,%1,%2,%3};"
                 : "+f"(c[0]), "+f"(c[1]), "+f"(c[2]), "+f"(c[3])
                 : "r"(a[0]), "r"(a[1]), "r"(a[2]), "r"(a[3]), "r"(b[0]), "r"(b[1]));
}
__device__ __forceinline__ void cp_async16(uint32_t dst, const void* src) {
    asm volatile("cp.async.cg.shared.global [%0], [%1], 16;"
                 :: "r"(dst), "l"((size_t)__cvta_generic_to_global(src)) : "memory");
}
#define CP_COMMIT() asm volatile("cp.async.commit_group;" ::: "memory")
#define CP_WAIT0()  asm volatile("cp.async.wait_group 0;" ::: "memory")
#define CP_WAIT1()  asm volatile("cp.async.wait_group 1;" ::: "memory")

__device__ __forceinline__ float tanh_fast(float x) {
    float y;
    asm("tanh.approx.f32 %0, %1;" : "=f"(y) : "f"(x));
    return y;
}

// ---------------------------------------------------------------------------
// Prep kernels: fp16 conversion with zero padding (16B stores)
// ---------------------------------------------------------------------------
__device__ __forceinline__ void cvt8_store(__half* dst, const float* src, int k8) {
    uint4 out;
    __half2 h[4];
    if (k8 < 37) {
        float4 a = *(const float4*)(src);
        float4 b = *(const float4*)(src + 4);
        h[0] = __floats2half2_rn(a.x, a.y);
        h[1] = __floats2half2_rn(a.z, a.w);
        h[2] = __floats2half2_rn(b.x, b.y);
        h[3] = __floats2half2_rn(b.z, b.w);
    } else if (k8 == 37) {
        float4 a = *(const float4*)(src);
        h[0] = __floats2half2_rn(a.x, a.y);
        h[1] = __floats2half2_rn(a.z, a.w);
        h[2] = __floats2half2_rn(0.f, 0.f);
        h[3] = h[2];
    } else {
        h[0] = __floats2half2_rn(0.f, 0.f);
        h[1] = h[0]; h[2] = h[0]; h[3] = h[0];
    }
    memcpy(&out, h, 16);
    *(uint4*)dst = out;
}

__global__ __launch_bounds__(256)
void prep_seq_kernel(const float* __restrict__ seq)
{
    size_t gid = (size_t)blockIdx.x * 256 + threadIdx.x;
    if (gid >= (size_t)M_SEQ * (DPAD / 8)) return;
    size_t row = gid / (DPAD / 8);
    int k8 = (int)(gid % (DPAD / 8));
    cvt8_store(g_seqh + row * DPAD + k8 * 8, seq + row * D + (size_t)k8 * 8, k8);
}

__global__ __launch_bounds__(256)
void prep_vec_kernel(const float* __restrict__ vec)
{
    size_t gid = (size_t)blockIdx.x * 256 + threadIdx.x;
    if (gid >= (size_t)M_VEC * (DPAD / 8)) return;
    size_t row = gid / (DPAD / 8);
    int k8 = (int)(gid % (DPAD / 8));
    cvt8_store(g_vech + row * DPAD + k8 * 8, vec + row * D + (size_t)k8 * 8, k8);
}

__global__ __launch_bounds__(256)
void prep_w_kernel(const float* __restrict__ W)
{
    int idx = blockIdx.x * 256 + threadIdx.x;
    if (idx >= DPAD * DPAD) return;
    int o = idx / DPAD, k = idx - o * DPAD;
    float ws = 0.f, wv = 0.f;
    if (o < D && k < D) {
        ws = W[(size_t)o * 600 + k];
        wv = W[(size_t)o * 600 + 300 + k];
    }
    g_Ws[idx] = __float2half_rn(ws);
    g_Wv[idx] = __float2half_rn(wv);
}

// ---------------------------------------------------------------------------
// score kernel: full-o CTA. m-tile 160, all 320 o per CTA.
// smem: A resident (5 k-chunks), B double-buffered per o-tile.
// row stride 72 halfs (144B) — conflict-free ldmatrix.
// ---------------------------------------------------------------------------
#define MROWS 160
#define ACHUNK (MROWS * 144)             // 23040 per k-chunk
#define SM_A 0                           // 5 chunks = 115200
#define BB   (5 * 64 * 144)              // 46080 per B buffer (5 k-chunks)
#define SM_B (5 * ACHUNK)                // 115200
#define SVPS (SM_B + 2 * BB)             // 207360: 8 x 320 fp32
#define SVS  (SVPS + 8 * 320 * 4)        // 217600: 320 fp32
#define SMEM_SCORE (SVS + 320 * 4)       // 218880

__device__ __forceinline__ void stage_B_ot(uint32_t sb, int buf, int ot)
{
    const int tid = threadIdx.x;
    const uint32_t base = sb + SM_B + (uint32_t)buf * BB;
#pragma unroll
    for (int q = 0; q < 8; q++) {         // 2560 segs / 320 thr
        int it = tid + q * 320;
        int kc = it >> 9;                 // /512
        int w = it & 511;
        int r = w >> 3, s = w & 7;
        cp_async16(base + (uint32_t)(kc * 9216 + r * 144 + s * 16),
                   g_Ws + (size_t)(ot * 64 + r) * DPAD + kc * 64 + s * 8);
    }
}

__global__ __launch_bounds__(320, 1)
void score_mma_kernel(const float* __restrict__ v)
{
    extern __shared__ char smem[];
    const uint32_t sb = smem_u32(smem);
    const int tid = threadIdx.x;
    const int wid = tid >> 5, lid = tid & 31;
    const int m0 = blockIdx.x * MROWS;
    const int bs0 = m0 / WL;              // 8 bs rows per tile (160 = 8*20)
    const int wm = wid * 16;

    float* vps = (float*)(smem + SVPS);   // [8][320]
    float* vsm = (float*)(smem + SVS);    // [320]

    // Prologue: stage ALL of A (5 chunks) + B(ot=0) in one group
    {
#pragma unroll
        for (int q = 0; q < 4; q++) {     // per chunk: 1280 segs / 320 thr
            int it = tid + q * 320;
            int r = it >> 3, s = it & 7;
#pragma unroll
            for (int kc = 0; kc < 5; kc++)
                cp_async16(sb + SM_A + (uint32_t)(kc * ACHUNK + r * 144 + s * 16),
                           g_seqh + (size_t)(m0 + r) * DPAD + kc * 64 + s * 8);
        }
        stage_B_ot(sb, 0, 0);
        CP_COMMIT();
    }

    // vps (zero-padded to 320) and v
    for (int it = tid; it < 8 * 320; it += 320) {
        int r = it >> 8 << 0;             // it/320
        r = it / 320;
        int oc = it - r * 320;
        vps[it] = (oc < D) ? g_vecpart[(size_t)(bs0 + r) * D + oc] : 0.f;
    }
    if (tid < 320) vsm[tid] = (tid < D) ? v[tid] : 0.f;

    // ldmatrix lane addressing
    const int a_row = ((lid >> 3) & 1) * 8 + (lid & 7);
    const int a_col = (lid >> 4) * 8;
    const int b_row = (lid >> 4) * 8 + (lid & 7);
    const int b_col = ((lid >> 3) & 1) * 8;
    const uint32_t aAoff = (uint32_t)((wm + a_row) * 144 + a_col * 2);
    const uint32_t aBoff = (uint32_t)(b_row * 144 + b_col * 2);

    const int g = lid >> 2, t = lid & 3;
    const int r0 = wm + g, r1 = wm + 8 + g;
    const int bsl0 = r0 / WL, bsl1 = r1 / WL;
    const float* vp0 = vps + bsl0 * 320;
    const float* vp1 = vps + bsl1 * 320;

    float p0 = 0.f, p1 = 0.f;             // total score, accumulated over ot

    for (int ot = 0; ot < 5; ot++) {
        const int buf = ot & 1;

        if (ot + 1 < 5) {
            stage_B_ot(sb, (ot + 1) & 1, ot + 1);
            CP_COMMIT();
            CP_WAIT1();                   // A + B(ot) arrived
        } else {
            CP_WAIT0();
        }
        __syncthreads();                  // everyone's staging visible

        float acc[8][4];
#pragma unroll
        for (int j = 0; j < 8; j++)
#pragma unroll
            for (int q = 0; q < 4; q++) acc[j][q] = 0.f;

        const uint32_t bbase = sb + SM_B + (uint32_t)buf * BB;
#pragma unroll
        for (int kc = 0; kc < 5; kc++) {
            const uint32_t abase = sb + SM_A + (uint32_t)kc * ACHUNK;
            const uint32_t bkc = bbase + (uint32_t)kc * 9216;
#pragma unroll
            for (int ks = 0; ks < 4; ks++) {
                const uint32_t kb = (uint32_t)ks * 32;
                uint32_t a0[4];
                ldsm_x4(a0, abase + aAoff + kb);
#pragma unroll
                for (int p = 0; p < 4; p++) {
                    uint32_t b[4];
                    ldsm_x4(b, bkc + aBoff + kb + (uint32_t)(p * 16 * 144));
                    mma_f16(acc[2*p],   a0, b);
                    mma_f16(acc[2*p+1], a0, b + 2);
                }
            }
        }

        // Branch-free epilogue for this o-tile (padding contributes 0)
        const int o0 = ot * 64;
#pragma unroll
        for (int j = 0; j < 8; j++) {
            int oc = o0 + j * 8 + 2 * t;
            float v0 = vsm[oc], v1 = vsm[oc + 1];
            p0 += tanh_fast(acc[j][0] + vp0[oc]) * v0
                + tanh_fast(acc[j][1] + vp0[oc + 1]) * v1;
            p1 += tanh_fast(acc[j][2] + vp1[oc]) * v0
                + tanh_fast(acc[j][3] + vp1[oc + 1]) * v1;
        }

        __syncthreads();                  // reads of buf done before its reuse
    }

    p0 += __shfl_xor_sync(0xffffffffu, p0, 1);
    p0 += __shfl_xor_sync(0xffffffffu, p0, 2);
    p1 += __shfl_xor_sync(0xffffffffu, p1, 1);
    p1 += __shfl_xor_sync(0xffffffffu, p1, 2);
    if (t == 0) {
        g_score[m0 + r0] = p0;
        g_score[m0 + r1] = p1;
    }
}

// ---------------------------------------------------------------------------
// vecpart via fp16 HMMA. grid = (64, 5): m-tiles of 64, 4 warps (m16 each).
// ---------------------------------------------------------------------------
#define ASTRIDE 72
#define VABUF (64 * ASTRIDE * 2)         // 9216
#define VBBUF (64 * ASTRIDE * 2)         // 9216
#define VSM_B (2 * VABUF)                // 18432
#define VSM_BIAS (2 * VABUF + 2 * VBBUF) // 36864
#define SMEM_VECP (VSM_BIAS + 256)       // 37120

__device__ __forceinline__ void vstage(uint32_t abase, uint32_t bbase,
                                       int m0, int o0, int k0)
{
    const int tid = threadIdx.x;
#pragma unroll
    for (int q = 0; q < 4; q++) {
        int it = tid + q * 128;
        int r = it >> 3, s = it & 7;
        cp_async16(abase + (uint32_t)(r * 144 + s * 16),
                   g_vech + (size_t)(m0 + r) * DPAD + k0 + s * 8);
    }
#pragma unroll
    for (int q = 0; q < 4; q++) {
        int it = tid + q * 128;
        int r = it >> 3, s = it & 7;
        cp_async16(bbase + (uint32_t)(r * 144 + s * 16),
                   g_Wv + (size_t)(o0 + r) * DPAD + k0 + s * 8);
    }
    CP_COMMIT();
}

__global__ __launch_bounds__(128, 4)
void vecpart_mma_kernel(const float* __restrict__ bias)
{
    extern __shared__ char smem[];
    const uint32_t sb = smem_u32(smem);
    const int tid = threadIdx.x;
    const int wid = tid >> 5, lid = tid & 31;
    const int m0 = blockIdx.x * 64;
    const int o0 = blockIdx.y * 64;
    const int wm = wid * 16;

    float* bsm = (float*)(smem + VSM_BIAS);

    vstage(sb, sb + VSM_B, m0, o0, 0);

    if (tid < 64) bsm[tid] = (o0 + tid < D) ? bias[o0 + tid] : 0.f;

    CP_WAIT0();
    __syncthreads();

    const int a_row = ((lid >> 3) & 1) * 8 + (lid & 7);
    const int a_col = (lid >> 4) * 8;
    const int b_row = (lid >> 4) * 8 + (lid & 7);
    const int b_col = ((lid >> 3) & 1) * 8;
    const uint32_t aAoff = (uint32_t)((wm + a_row) * 144 + a_col * 2);
    const uint32_t aBoff = (uint32_t)(b_row * 144 + b_col * 2);

    const int g = lid >> 2, t = lid & 3;
    const int r0 = wm + g, r1 = wm + 8 + g;

    float acc[8][4];
#pragma unroll
    for (int j = 0; j < 8; j++)
#pragma unroll
        for (int q = 0; q < 4; q++) acc[j][q] = 0.f;

    for (int c = 0; c < 5; c++) {
        const int buf = c & 1;
        if (c + 1 < 5) {
            vstage(sb + (((c + 1) & 1) ? VABUF : 0),
                   sb + VSM_B + (((c + 1) & 1) ? VBBUF : 0),
                   m0, o0, (c + 1) * 64);
            CP_WAIT1();
        } else {
            CP_WAIT0();
        }
        __syncthreads();

        const uint32_t abase = sb + (buf ? VABUF : 0);
        const uint32_t bbase = sb + VSM_B + (buf ? VBBUF : 0);
#pragma unroll
        for (int ks = 0; ks < 4; ks++) {
            const uint32_t kb = (uint32_t)ks * 32;
            uint32_t a0[4];
            ldsm_x4(a0, abase + aAoff + kb);
#pragma unroll
            for (int p = 0; p < 4; p++) {
                uint32_t b[4];
                ldsm_x4(b, bbase + aBoff + kb + (uint32_t)(p * 16 * 144));
                mma_f16(acc[2*p],   a0, b);
                mma_f16(acc[2*p+1], a0, b + 2);
            }
        }
        __syncthreads();
    }

#pragma unroll
    for (int j = 0; j < 8; j++) {
        int oc = j * 8 + 2 * t;
        int o = o0 + oc;
        if (o < D) {
            float bb = bsm[oc];
            g_vecpart[(size_t)(m0 + r0) * D + o] = acc[j][0] + bb;
            g_vecpart[(size_t)(m0 + r1) * D + o] = acc[j][2] + bb;
        }
        if (o + 1 < D) {
            float bb = bsm[oc + 1];
            g_vecpart[(size_t)(m0 + r0) * D + o + 1] = acc[j][1] + bb;
            g_vecpart[(size_t)(m0 + r1) * D + o + 1] = acc[j][3] + bb;
        }
    }
}

// ---------------------------------------------------------------------------
// Kernel: masked softmax over w (20) + weighted = alphas · seq
// ---------------------------------------------------------------------------
__global__ __launch_bounds__(128)
void softmax_weighted_kernel(const float* __restrict__ seq,
                             const int* __restrict__ masks,
                             float* __restrict__ out)
{
    const int bs = blockIdx.x;
    const int t = threadIdx.x;
    __shared__ float al[WL];

    if (t < 32) {
        float s = -1e30f;
        if (t < WL) {
            s = g_score[bs * WL + t];
            if (masks[bs * WL + t] == 0) s = NEG_INF;
        }
        float mx = s;
#pragma unroll
        for (int off = 16; off > 0; off >>= 1)
            mx = fmaxf(mx, __shfl_xor_sync(0xffffffffu, mx, off));
        float e = (t < WL) ? expf(s - mx) : 0.f;
        float sum = e;
#pragma unroll
        for (int off = 16; off > 0; off >>= 1)
            sum += __shfl_xor_sync(0xffffffffu, sum, off);
        if (t < WL) al[t] = e / sum;
    }
    __syncthreads();

    const float* base = seq + (size_t)bs * WL * D;
    for (int d = t; d < D; d += 128) {
        float a = 0.f;
#pragma unroll
        for (int w = 0; w < WL; w++) a += al[w] * base[w * D + d];
        out[(size_t)bs * D + d] = a;
    }
}

// ---------------------------------------------------------------------------
extern "C" void kernel_launch(void* const* d_in, const int* in_sizes, int n_in,
                              void* d_out, int out_size)
{
    const float* seq   = (const float*)d_in[0];
    const float* vec   = (const float*)d_in[1];
    const int*   masks = (const int*)  d_in[2];
    const float* W     = (const float*)d_in[3];
    const float* bias  = (const float*)d_in[4];
    const float* v     = (const float*)d_in[5];
    float* out = (float*)d_out;

    cudaFuncSetAttribute(score_mma_kernel,
                         cudaFuncAttributeMaxDynamicSharedMemorySize, SMEM_SCORE);
    cudaFuncSetAttribute(vecpart_mma_kernel,
                         cudaFuncAttributeMaxDynamicSharedMemorySize, SMEM_VECP);

    prep_w_kernel<<<(DPAD * DPAD + 255) / 256, 256>>>(W);
    prep_seq_kernel<<<(int)(((size_t)M_SEQ * (DPAD / 8) + 255) / 256), 256>>>(seq);
    prep_vec_kernel<<<(int)(((size_t)M_VEC * (DPAD / 8) + 255) / 256), 256>>>(vec);
    vecpart_mma_kernel<<<dim3(M_VEC / 64, 5), 128, SMEM_VECP>>>(bias);
    score_mma_kernel<<<M_SEQ / MROWS, 320, SMEM_SCORE>>>(v);
    softmax_weighted_kernel<<<M_VEC, 128>>>(seq, masks, out);
}

// round 9
// speedup vs baseline: 1.1518x; 1.1518x over previous
#include <cuda_runtime.h>
#include <cuda_fp16.h>
#include <math.h>
#include <stdint.h>

// Problem constants
#define BATCH 32
#define SEQ   128
#define WL    20
#define D     300
#define DPAD  320
#define M_SEQ (BATCH*SEQ*WL)      // 81920
#define M_VEC (BATCH*SEQ)         // 4096
#define NEG_INF -1000000000.0f

// Scratch (__device__ globals — no cudaMalloc allowed)
// +64 pad: score epilogue reads vecpart rows with o up to 319 (zero-padded v
// makes those terms 0, but the load must stay in bounds).
__device__ float g_vecpart[M_VEC * D + 64];
__device__ float g_score[M_SEQ];
__device__ __align__(16) __half g_Ws[DPAD * DPAD];
__device__ __align__(16) __half g_Wv[DPAD * DPAD];
__device__ __align__(16) __half g_seqh[(size_t)M_SEQ * DPAD];
__device__ __align__(16) __half g_vech[(size_t)M_VEC * DPAD];

// ---------------------------------------------------------------------------
// PTX helpers (sm_80-era — valid at plain sm_103 target)
// ---------------------------------------------------------------------------
__device__ __forceinline__ uint32_t smem_u32(const void* p) {
    uint32_t a;
    asm("{ .reg .u64 t; cvta.to.shared.u64 t, %1; cvt.u32.u64 %0, t; }" : "=r"(a) : "l"(p));
    return a;
}
__device__ __forceinline__ void ldsm_x4(uint32_t* r, uint32_t addr) {
    asm volatile("ldmatrix.sync.aligned.m8n8.x4.shared.b16 {%0,%1,%2,%3}, [%4];"
                 : "=r"(r[0]), "=r"(r[1]), "=r"(r[2]), "=r"(r[3]) : "r"(addr));
}
__device__ __forceinline__ void mma_f16(float* c, const uint32_t* a, const uint32_t* b) {
    asm volatile("mma.sync.aligned.m16n8k16.row.col.f32.f16.f16.f32 "
                 "{%0,%1,%2,%3}, {%4,%5,%6,%7}, {%8,%9}, {%0,%1,%2,%3};"
                 : "+f"(c[0]), "+f"(c[1]), "+f"(c[2]), "+f"(c[3])
                 : "r"(a[0]), "r"(a[1]), "r"(a[2]), "r"(a[3]), "r"(b[0]), "r"(b[1]));
}
__device__ __forceinline__ void cp_async16(uint32_t dst, const void* src) {
    asm volatile("cp.async.cg.shared.global [%0], [%1], 16;"
                 :: "r"(dst), "l"((size_t)__cvta_generic_to_global(src)) : "memory");
}
#define CP_COMMIT() asm volatile("cp.async.commit_group;" ::: "memory")
#define CP_WAIT0()  asm volatile("cp.async.wait_group 0;" ::: "memory")
#define CP_WAIT1()  asm volatile("cp.async.wait_group 1;" ::: "memory")

__device__ __forceinline__ float tanh_fast(float x) {
    float y;
    asm("tanh.approx.f32 %0, %1;" : "=f"(y) : "f"(x));
    return y;
}

// ---------------------------------------------------------------------------
// Prep kernels: fp16 conversion with zero padding (16B stores)
// ---------------------------------------------------------------------------
__device__ __forceinline__ void cvt8_store(__half* dst, const float* src, int k8) {
    uint4 out;
    __half2 h[4];
    if (k8 < 37) {
        float4 a = *(const float4*)(src);
        float4 b = *(const float4*)(src + 4);
        h[0] = __floats2half2_rn(a.x, a.y);
        h[1] = __floats2half2_rn(a.z, a.w);
        h[2] = __floats2half2_rn(b.x, b.y);
        h[3] = __floats2half2_rn(b.z, b.w);
    } else if (k8 == 37) {
        float4 a = *(const float4*)(src);
        h[0] = __floats2half2_rn(a.x, a.y);
        h[1] = __floats2half2_rn(a.z, a.w);
        h[2] = __floats2half2_rn(0.f, 0.f);
        h[3] = h[2];
    } else {
        h[0] = __floats2half2_rn(0.f, 0.f);
        h[1] = h[0]; h[2] = h[0]; h[3] = h[0];
    }
    memcpy(&out, h, 16);
    *(uint4*)dst = out;
}

__global__ __launch_bounds__(256)
void prep_seq_kernel(const float* __restrict__ seq)
{
    size_t gid = (size_t)blockIdx.x * 256 + threadIdx.x;
    if (gid >= (size_t)M_SEQ * (DPAD / 8)) return;
    size_t row = gid / (DPAD / 8);
    int k8 = (int)(gid % (DPAD / 8));
    cvt8_store(g_seqh + row * DPAD + k8 * 8, seq + row * D + (size_t)k8 * 8, k8);
}

__global__ __launch_bounds__(256)
void prep_vec_kernel(const float* __restrict__ vec)
{
    size_t gid = (size_t)blockIdx.x * 256 + threadIdx.x;
    if (gid >= (size_t)M_VEC * (DPAD / 8)) return;
    size_t row = gid / (DPAD / 8);
    int k8 = (int)(gid % (DPAD / 8));
    cvt8_store(g_vech + row * DPAD + k8 * 8, vec + row * D + (size_t)k8 * 8, k8);
}

__global__ __launch_bounds__(256)
void prep_w_kernel(const float* __restrict__ W)
{
    int idx = blockIdx.x * 256 + threadIdx.x;
    if (idx >= DPAD * DPAD) return;
    int o = idx / DPAD, k = idx - o * DPAD;
    float ws = 0.f, wv = 0.f;
    if (o < D && k < D) {
        ws = W[(size_t)o * 600 + k];
        wv = W[(size_t)o * 600 + 300 + k];
    }
    g_Ws[idx] = __float2half_rn(ws);
    g_Wv[idx] = __float2half_rn(wv);
}

// ---------------------------------------------------------------------------
// score kernel: m-tile 128, A resident across full K (staged once),
// loop over 5 o-parts x 5 k-chunks with double-buffered 64x64 B tiles.
// 8 warps, warp m16 x n64. Score accumulated in regs over all o.
// smem: A 5x18432=92160, B 2x9216=18432, v 1280  => 111872 B, 2 CTAs/SM.
// ---------------------------------------------------------------------------
#define ACHUNK (128 * 144)               // 18432
#define SM_A 0
#define SM_B (5 * ACHUNK)                // 92160
#define SVS  (SM_B + 2 * 9216)           // 110592
#define SMEM_SCORE (SVS + 320 * 4)       // 111872

__device__ __forceinline__ void stage_B(uint32_t sb, int buf, int ot, int kc)
{
    const int tid = threadIdx.x;
    const uint32_t base = sb + SM_B + (uint32_t)buf * 9216;
#pragma unroll
    for (int q = 0; q < 2; q++) {        // 512 segs / 256 thr
        int it = tid + q * 256;
        int r = it >> 3, s = it & 7;
        cp_async16(base + (uint32_t)(r * 144 + s * 16),
                   g_Ws + (size_t)(ot * 64 + r) * DPAD + kc * 64 + s * 8);
    }
    CP_COMMIT();
}

__global__ __launch_bounds__(256, 2)
void score_mma_kernel(const float* __restrict__ v)
{
    extern __shared__ char smem[];
    const uint32_t sb = smem_u32(smem);
    const int tid = threadIdx.x;
    const int wid = tid >> 5, lid = tid & 31;
    const int m0 = blockIdx.x * 128;
    const int wm = wid * 16;

    float* vsm = (float*)(smem + SVS);   // [320], zero-padded

    // Prologue: stage ALL A chunks (once) + B(0,0)
    {
#pragma unroll
        for (int q = 0; q < 20; q++) {   // 5 chunks * 1024 segs / 256 thr
            int it = tid + q * 256;
            int kc = it >> 10;
            int w = it & 1023;
            int r = w >> 3, s = w & 7;
            cp_async16(sb + SM_A + (uint32_t)(kc * ACHUNK + r * 144 + s * 16),
                       g_seqh + (size_t)(m0 + r) * DPAD + kc * 64 + s * 8);
        }
        stage_B(sb, 0, 0, 0);            // commits A+B together
    }

    for (int it = tid; it < 320; it += 256)
        vsm[it] = (it < D) ? v[it] : 0.f;

    CP_WAIT0();
    __syncthreads();

    // ldmatrix lane addressing
    const int a_row = ((lid >> 3) & 1) * 8 + (lid & 7);
    const int a_col = (lid >> 4) * 8;
    const int b_row = (lid >> 4) * 8 + (lid & 7);
    const int b_col = ((lid >> 3) & 1) * 8;
    const uint32_t aAoff = (uint32_t)((wm + a_row) * 144 + a_col * 2);
    const uint32_t aBoff = (uint32_t)(b_row * 144 + b_col * 2);

    const int g = lid >> 2, t = lid & 3;
    const int r0 = wm + g, r1 = wm + 8 + g;
    const float* vp0 = g_vecpart + (size_t)((m0 + r0) / WL) * D;
    const float* vp1 = g_vecpart + (size_t)((m0 + r1) / WL) * D;

    float p0 = 0.f, p1 = 0.f;            // full score accumulators
    float acc[8][4];

    for (int i = 0; i < 25; i++) {
        const int ot = i / 5, kc = i - ot * 5, buf = i & 1;

        if (kc == 0) {
#pragma unroll
            for (int j = 0; j < 8; j++)
#pragma unroll
                for (int q = 0; q < 4; q++) acc[j][q] = 0.f;
        }

        // Prefetch next B into other buffer (overlaps with MMA below)
        if (i + 1 < 25) {
            int ni = i + 1, not_ = ni / 5, nkc = ni - not_ * 5;
            stage_B(sb, ni & 1, not_, nkc);
        }

        const uint32_t abase = sb + SM_A + (uint32_t)kc * ACHUNK;
        const uint32_t bbase = sb + SM_B + (uint32_t)buf * 9216;
#pragma unroll
        for (int ks = 0; ks < 4; ks++) {
            const uint32_t kb = (uint32_t)ks * 32;
            uint32_t a0[4];
            ldsm_x4(a0, abase + aAoff + kb);
#pragma unroll
            for (int p = 0; p < 4; p++) {
                uint32_t b[4];
                ldsm_x4(b, bbase + aBoff + kb + (uint32_t)(p * 16 * 144));
                mma_f16(acc[2*p],   a0, b);
                mma_f16(acc[2*p+1], a0, b + 2);
            }
        }

        // End of o-part: tanh(lin)*v (branch-free: padded o terms are 0)
        if (kc == 4) {
            const int o0 = ot * 64;
#pragma unroll
            for (int j = 0; j < 8; j++) {
                int o = o0 + j * 8 + 2 * t;
                float v0 = vsm[o], v1 = vsm[o + 1];
                p0 += tanh_fast(acc[j][0] + __ldg(vp0 + o)) * v0
                    + tanh_fast(acc[j][1] + __ldg(vp0 + o + 1)) * v1;
                p1 += tanh_fast(acc[j][2] + __ldg(vp1 + o)) * v0
                    + tanh_fast(acc[j][3] + __ldg(vp1 + o + 1)) * v1;
            }
        }

        CP_WAIT0();
        __syncthreads();
    }

    p0 += __shfl_xor_sync(0xffffffffu, p0, 1);
    p0 += __shfl_xor_sync(0xffffffffu, p0, 2);
    p1 += __shfl_xor_sync(0xffffffffu, p1, 1);
    p1 += __shfl_xor_sync(0xffffffffu, p1, 2);
    if (t == 0) {
        g_score[m0 + r0] = p0;
        g_score[m0 + r1] = p1;
    }
}

// ---------------------------------------------------------------------------
// vecpart via fp16 HMMA. grid = (64, 5): m-tiles of 64, 4 warps (m16 each).
// (unchanged from R7 — 11-12 us)
// ---------------------------------------------------------------------------
#define ASTRIDE 72
#define VABUF (64 * ASTRIDE * 2)         // 9216
#define VBBUF (64 * ASTRIDE * 2)         // 9216
#define VSM_B (2 * VABUF)                // 18432
#define VSM_BIAS (2 * VABUF + 2 * VBBUF) // 36864
#define SMEM_VECP (VSM_BIAS + 256)       // 37120

__device__ __forceinline__ void vstage(uint32_t abase, uint32_t bbase,
                                       int m0, int o0, int k0)
{
    const int tid = threadIdx.x;
#pragma unroll
    for (int q = 0; q < 4; q++) {
        int it = tid + q * 128;
        int r = it >> 3, s = it & 7;
        cp_async16(abase + (uint32_t)(r * 144 + s * 16),
                   g_vech + (size_t)(m0 + r) * DPAD + k0 + s * 8);
    }
#pragma unroll
    for (int q = 0; q < 4; q++) {
        int it = tid + q * 128;
        int r = it >> 3, s = it & 7;
        cp_async16(bbase + (uint32_t)(r * 144 + s * 16),
                   g_Wv + (size_t)(o0 + r) * DPAD + k0 + s * 8);
    }
    CP_COMMIT();
}

__global__ __launch_bounds__(128, 4)
void vecpart_mma_kernel(const float* __restrict__ bias)
{
    extern __shared__ char smem[];
    const uint32_t sb = smem_u32(smem);
    const int tid = threadIdx.x;
    const int wid = tid >> 5, lid = tid & 31;
    const int m0 = blockIdx.x * 64;
    const int o0 = blockIdx.y * 64;
    const int wm = wid * 16;

    float* bsm = (float*)(smem + VSM_BIAS);

    vstage(sb, sb + VSM_B, m0, o0, 0);

    if (tid < 64) bsm[tid] = (o0 + tid < D) ? bias[o0 + tid] : 0.f;

    CP_WAIT0();
    __syncthreads();

    const int a_row = ((lid >> 3) & 1) * 8 + (lid & 7);
    const int a_col = (lid >> 4) * 8;
    const int b_row = (lid >> 4) * 8 + (lid & 7);
    const int b_col = ((lid >> 3) & 1) * 8;
    const uint32_t aAoff = (uint32_t)((wm + a_row) * 144 + a_col * 2);
    const uint32_t aBoff = (uint32_t)(b_row * 144 + b_col * 2);

    const int g = lid >> 2, t = lid & 3;
    const int r0 = wm + g, r1 = wm + 8 + g;

    float acc[8][4];
#pragma unroll
    for (int j = 0; j < 8; j++)
#pragma unroll
        for (int q = 0; q < 4; q++) acc[j][q] = 0.f;

    for (int c = 0; c < 5; c++) {
        const int buf = c & 1;
        if (c + 1 < 5)
            vstage(sb + (((c + 1) & 1) ? VABUF : 0),
                   sb + VSM_B + (((c + 1) & 1) ? VBBUF : 0),
                   m0, o0, (c + 1) * 64);

        const uint32_t abase = sb + (buf ? VABUF : 0);
        const uint32_t bbase = sb + VSM_B + (buf ? VBBUF : 0);
#pragma unroll
        for (int ks = 0; ks < 4; ks++) {
            const uint32_t kb = (uint32_t)ks * 32;
            uint32_t a0[4];
            ldsm_x4(a0, abase + aAoff + kb);
#pragma unroll
            for (int p = 0; p < 4; p++) {
                uint32_t b[4];
                ldsm_x4(b, bbase + aBoff + kb + (uint32_t)(p * 16 * 144));
                mma_f16(acc[2*p],   a0, b);
                mma_f16(acc[2*p+1], a0, b + 2);
            }
        }
        CP_WAIT0();
        __syncthreads();
    }

#pragma unroll
    for (int j = 0; j < 8; j++) {
        int oc = j * 8 + 2 * t;
        int o = o0 + oc;
        if (o < D) {
            float bb = bsm[oc];
            g_vecpart[(size_t)(m0 + r0) * D + o] = acc[j][0] + bb;
            g_vecpart[(size_t)(m0 + r1) * D + o] = acc[j][2] + bb;
        }
        if (o + 1 < D) {
            float bb = bsm[oc + 1];
            g_vecpart[(size_t)(m0 + r0) * D + o + 1] = acc[j][1] + bb;
            g_vecpart[(size_t)(m0 + r1) * D + o + 1] = acc[j][3] + bb;
        }
    }
}

// ---------------------------------------------------------------------------
// Kernel: masked softmax over w (20) + weighted = alphas · seq (fp16 seq)
// ---------------------------------------------------------------------------
__global__ __launch_bounds__(128)
void softmax_weighted_kernel(const int* __restrict__ masks,
                             float* __restrict__ out)
{
    const int bs = blockIdx.x;
    const int t = threadIdx.x;
    __shared__ float al[WL];

    if (t < 32) {
        float s = -1e30f;
        if (t < WL) {
            s = g_score[bs * WL + t];
            if (masks[bs * WL + t] == 0) s = NEG_INF;
        }
        float mx = s;
#pragma unroll
        for (int off = 16; off > 0; off >>= 1)
            mx = fmaxf(mx, __shfl_xor_sync(0xffffffffu, mx, off));
        float e = (t < WL) ? expf(s - mx) : 0.f;
        float sum = e;
#pragma unroll
        for (int off = 16; off > 0; off >>= 1)
            sum += __shfl_xor_sync(0xffffffffu, sum, off);
        if (t < WL) al[t] = e / sum;
    }
    __syncthreads();

    const __half* base = g_seqh + (size_t)bs * WL * DPAD;
    for (int d2 = t; d2 < D / 2; d2 += 128) {
        float a0 = 0.f, a1 = 0.f;
#pragma unroll
        for (int w = 0; w < WL; w++) {
            float2 x = __half22float2(*(const __half2*)(base + w * DPAD + d2 * 2));
            a0 += al[w] * x.x;
            a1 += al[w] * x.y;
        }
        out[(size_t)bs * D + d2 * 2]     = a0;
        out[(size_t)bs * D + d2 * 2 + 1] = a1;
    }
}

// ---------------------------------------------------------------------------
extern "C" void kernel_launch(void* const* d_in, const int* in_sizes, int n_in,
                              void* d_out, int out_size)
{
    const float* seq   = (const float*)d_in[0];
    const float* vec   = (const float*)d_in[1];
    const int*   masks = (const int*)  d_in[2];
    const float* W     = (const float*)d_in[3];
    const float* bias  = (const float*)d_in[4];
    const float* v     = (const float*)d_in[5];
    float* out = (float*)d_out;

    cudaFuncSetAttribute(score_mma_kernel,
                         cudaFuncAttributeMaxDynamicSharedMemorySize, SMEM_SCORE);
    cudaFuncSetAttribute(vecpart_mma_kernel,
                         cudaFuncAttributeMaxDynamicSharedMemorySize, SMEM_VECP);

    prep_w_kernel<<<(DPAD * DPAD + 255) / 256, 256>>>(W);
    prep_seq_kernel<<<(int)(((size_t)M_SEQ * (DPAD / 8) + 255) / 256), 256>>>(seq);
    prep_vec_kernel<<<(int)(((size_t)M_VEC * (DPAD / 8) + 255) / 256), 256>>>(vec);
    vecpart_mma_kernel<<<dim3(M_VEC / 64, 5), 128, SMEM_VECP>>>(bias);
    score_mma_kernel<<<M_SEQ / 128, 256, SMEM_SCORE>>>(v);
    softmax_weighted_kernel<<<M_VEC, 128>>>(masks, out);
}